// round 13
// baseline (speedup 1.0000x reference)
#include <cuda_runtime.h>

#define MAX_N 100000
#define MAX_E 1200000
#define MAX_EP (MAX_E + 3 * MAX_N)   // padded bins: each row rounded up to 4
#define FDIM 64

__device__ float g_Q[(size_t)MAX_N * FDIM];      // Q = X@W1 + (X*X)@W2
__device__ int   g_cnt[MAX_N];                   // per-row edge count
__device__ int   g_rowstart[MAX_N];              // exclusive scan of padded counts
__device__ int   g_cursor[MAX_N];                // scatter cursor
__device__ int2  g_edges[MAX_EP];                // binned (col, val), zero-padded to x4
__device__ int   g_bsum[128];                    // raw per-block totals

// ---- packed f32x2 helpers (sm_103a FFMA2: 2 fp32 FMAs / issue slot) ----
typedef unsigned long long u64;
__device__ __forceinline__ u64 pack2(float lo, float hi) {
    u64 r; asm("mov.b64 %0, {%1, %2};" : "=l"(r) : "f"(lo), "f"(hi)); return r;
}
__device__ __forceinline__ void unpack2(u64 p, float& lo, float& hi) {
    asm("mov.b64 {%0, %1}, %2;" : "=f"(lo), "=f"(hi) : "l"(p));
}
__device__ __forceinline__ u64 fma2(u64 a, u64 b, u64 c) {
    u64 d; asm("fma.rn.f32x2 %0, %1, %2, %3;" : "=l"(d) : "l"(a), "l"(b), "l"(c)); return d;
}
__device__ __forceinline__ u64 mul2(u64 a, u64 b) {
    u64 d; asm("mul.rn.f32x2 %0, %1, %2;" : "=l"(d) : "l"(a), "l"(b)); return d;
}

// ---------------------------------------------------------------------------
// Dense GEMM (f32x2) + fused histogram. (R8/R12 measured-best, byte-identical)
// ---------------------------------------------------------------------------
__global__ __launch_bounds__(256, 3) void gnn_dense_hist(
    const float* __restrict__ X,
    const float* __restrict__ W1, const float* __restrict__ b1,
    const float* __restrict__ W2, const float* __restrict__ b2,
    const int* __restrict__ rows,
    float* __restrict__ out, int N, int E)
{
    extern __shared__ float smem[];
    float* W1s = smem;          // 64*64 = 16KB
    float* W2s = smem + 4096;   // 16KB
    float* Xs  = smem + 8192;   // 64*64 = 16KB

    const int tid = threadIdx.x;

    #pragma unroll
    for (int i = tid; i < 1024; i += 256) {
        reinterpret_cast<float4*>(W1s)[i] = reinterpret_cast<const float4*>(W1)[i];
        reinterpret_cast<float4*>(W2s)[i] = reinterpret_cast<const float4*>(W2)[i];
    }

    const int row0 = blockIdx.x * 64;
    #pragma unroll
    for (int i = tid; i < 64 * 16; i += 256) {
        const int r  = i >> 4;
        const int gr = row0 + r;
        float4 v = make_float4(0.f, 0.f, 0.f, 0.f);
        if (gr < N) v = reinterpret_cast<const float4*>(X)[(size_t)gr * 16 + (i & 15)];
        reinterpret_cast<float4*>(Xs)[i] = v;
    }

    const int stride = gridDim.x * 256;
    for (int e = blockIdx.x * 256 + tid; e < E; e += stride)
        atomicAdd(&g_cnt[__ldg(rows + e)], 1);

    __syncthreads();

    const int rg  = (tid >> 4) * 4;
    const int cg4 = tid & 15;

    const u64* W1p = reinterpret_cast<const u64*>(W1s);
    const u64* W2p = reinterpret_cast<const u64*>(W2s);

    u64 acc1a[4], acc1b[4], acc2a[4], acc2b[4];
    #pragma unroll
    for (int i = 0; i < 4; ++i) { acc1a[i]=0; acc1b[i]=0; acc2a[i]=0; acc2b[i]=0; }

    #pragma unroll 8
    for (int k = 0; k < 64; ++k) {
        const u64 w1a = W1p[k * 32 + 2 * cg4];
        const u64 w1b = W1p[k * 32 + 2 * cg4 + 1];
        const u64 w2a = W2p[k * 32 + 2 * cg4];
        const u64 w2b = W2p[k * 32 + 2 * cg4 + 1];
        #pragma unroll
        for (int i = 0; i < 4; ++i) {
            const float x  = Xs[(rg + i) * 64 + k];
            const u64 xp  = pack2(x, x);
            const u64 xsq = mul2(xp, xp);
            acc1a[i] = fma2(xp,  w1a, acc1a[i]);
            acc1b[i] = fma2(xp,  w1b, acc1b[i]);
            acc2a[i] = fma2(xsq, w2a, acc2a[i]);
            acc2b[i] = fma2(xsq, w2b, acc2b[i]);
        }
    }

    const int cc = cg4 * 4;
    float4 bb;
    bb.x = __ldg(b1 + cc + 0) + __ldg(b2 + cc + 0);
    bb.y = __ldg(b1 + cc + 1) + __ldg(b2 + cc + 1);
    bb.z = __ldg(b1 + cc + 2) + __ldg(b2 + cc + 2);
    bb.w = __ldg(b1 + cc + 3) + __ldg(b2 + cc + 3);

    #pragma unroll
    for (int i = 0; i < 4; ++i) {
        const int gr = row0 + rg + i;
        if (gr < N) {
            float a10, a11, a12, a13, a20, a21, a22, a23;
            unpack2(acc1a[i], a10, a11);
            unpack2(acc1b[i], a12, a13);
            unpack2(acc2a[i], a20, a21);
            unpack2(acc2b[i], a22, a23);
            float4 o, q;
            o.x = a10 + bb.x;  q.x = a10 + a20;
            o.y = a11 + bb.y;  q.y = a11 + a21;
            o.z = a12 + bb.z;  q.z = a12 + a22;
            o.w = a13 + bb.w;  q.w = a13 + a23;
            reinterpret_cast<float4*>(out)[(size_t)gr * 16 + cg4] = o;
            reinterpret_cast<float4*>(g_Q)[(size_t)gr * 16 + cg4] = q;
        }
    }
}

// ---------------------------------------------------------------------------
// Scan: 2 kernels. blocksums publishes raw per-block totals of padded counts;
// scan_write sums its predecessors' totals itself (<=97 ints, lane-parallel,
// safe: written in the PREVIOUS launch).
// ---------------------------------------------------------------------------
__device__ __forceinline__ int warp_incl_scan(int v) {
    #pragma unroll
    for (int off = 1; off < 32; off <<= 1) {
        int u = __shfl_up_sync(0xffffffffu, v, off);
        if ((threadIdx.x & 31) >= off) v += u;
    }
    return v;
}

__global__ __launch_bounds__(1024) void scan_blocksums(int N) {
    const int i = blockIdx.x * 1024 + threadIdx.x;
    int v = (i < N) ? ((g_cnt[i] + 3) & ~3) : 0;
    #pragma unroll
    for (int off = 16; off > 0; off >>= 1)
        v += __shfl_down_sync(0xffffffffu, v, off);
    __shared__ int ws[32];
    const int lane = threadIdx.x & 31, wid = threadIdx.x >> 5;
    if (lane == 0) ws[wid] = v;
    __syncthreads();
    if (wid == 0) {
        int x = ws[lane];
        #pragma unroll
        for (int off = 16; off > 0; off >>= 1)
            x += __shfl_down_sync(0xffffffffu, x, off);
        if (lane == 0) g_bsum[blockIdx.x] = x;   // RAW total
    }
}

__global__ __launch_bounds__(1024) void scan_write(int N) {
    const int t = threadIdx.x, b = blockIdx.x;
    const int i = b * 1024 + t;
    const int cnt = (i < N) ? g_cnt[i] : 0;
    const int vp  = (cnt + 3) & ~3;
    const int lane = t & 31, wid = t >> 5;

    __shared__ int ws[32];
    __shared__ int s_pfx;

    // Predecessor block-total sum (raw totals from previous launch).
    if (wid == 0) {
        int s = 0;
        for (int j = lane; j < b; j += 32) s += g_bsum[j];
        #pragma unroll
        for (int off = 16; off > 0; off >>= 1)
            s += __shfl_down_sync(0xffffffffu, s, off);
        if (lane == 0) s_pfx = s;
    }

    int inc = warp_incl_scan(vp);
    if (lane == 31) ws[wid] = inc;
    __syncthreads();
    if (wid == 0) {
        int x = ws[lane];
        x = warp_incl_scan(x);
        ws[lane] = x;
    }
    __syncthreads();
    const int excl = inc - vp + (wid ? ws[wid - 1] : 0) + s_pfx;
    if (i < N) {
        g_rowstart[i] = excl;
        g_cursor[i]   = excl;
        const int2 z = make_int2(0, 0);
        for (int p = excl + cnt; p < excl + vp; ++p) g_edges[p] = z;
    }
}

__global__ __launch_bounds__(256) void gnn_scatter(
    const int* __restrict__ rows,
    const int* __restrict__ cols,
    const float* __restrict__ vals, int E)
{
    const int e = blockIdx.x * blockDim.x + threadIdx.x;
    if (e >= E) return;
    const int r   = __ldg(rows + e);
    const int pos = atomicAdd(&g_cursor[r], 1);
    g_edges[pos] = make_int2(__ldg(cols + e), __float_as_int(__ldg(vals + e)));
}

// ---------------------------------------------------------------------------
// CSR SpMM: 8 lanes per row, TWO float4 chunks per lane -> 8 independent
// gathers in flight per thread per 4-edge iteration. Padded bins keep the
// loop guard-free; next chunk's edges prefetched ahead of gathers.
// ---------------------------------------------------------------------------
__global__ __launch_bounds__(256) void gnn_spmm_csr(float* __restrict__ out, int N)
{
    const int gid = blockIdx.x * blockDim.x + threadIdx.x;
    const int row = gid >> 3;
    if (row >= N) return;
    const int p0 = (gid & 7) * 2;   // first float4 chunk index (0,2,...,14)

    const int start = __ldg(g_rowstart + row);
    const int end   = __ldg(g_cursor + row);      // = start + cnt
    const int deg   = end - start;
    if (deg <= 0) return;
    int iters = (deg + 3) >> 2;

    const float4* __restrict__ Q4 = reinterpret_cast<const float4*>(g_Q);
    const int2* ep = g_edges + start;

    int2 c0 = __ldg(ep + 0), c1 = __ldg(ep + 1);
    int2 c2 = __ldg(ep + 2), c3 = __ldg(ep + 3);

    float4 accA = make_float4(0.f, 0.f, 0.f, 0.f);
    float4 accB = make_float4(0.f, 0.f, 0.f, 0.f);

    while (--iters > 0) {
        ep += 4;
        const int2 n0 = __ldg(ep + 0), n1 = __ldg(ep + 1);
        const int2 n2 = __ldg(ep + 2), n3 = __ldg(ep + 3);

        const float4* r0 = Q4 + (size_t)c0.x * 16 + p0;
        const float4* r1 = Q4 + (size_t)c1.x * 16 + p0;
        const float4* r2 = Q4 + (size_t)c2.x * 16 + p0;
        const float4* r3 = Q4 + (size_t)c3.x * 16 + p0;
        const float4 a0 = __ldg(r0), b0 = __ldg(r0 + 1);
        const float4 a1 = __ldg(r1), b1 = __ldg(r1 + 1);
        const float4 a2 = __ldg(r2), b2 = __ldg(r2 + 1);
        const float4 a3 = __ldg(r3), b3 = __ldg(r3 + 1);
        const float v0 = __int_as_float(c0.y);
        const float v1 = __int_as_float(c1.y);
        const float v2 = __int_as_float(c2.y);
        const float v3 = __int_as_float(c3.y);

        accA.x = fmaf(v0, a0.x, accA.x); accA.y = fmaf(v0, a0.y, accA.y);
        accA.z = fmaf(v0, a0.z, accA.z); accA.w = fmaf(v0, a0.w, accA.w);
        accB.x = fmaf(v0, b0.x, accB.x); accB.y = fmaf(v0, b0.y, accB.y);
        accB.z = fmaf(v0, b0.z, accB.z); accB.w = fmaf(v0, b0.w, accB.w);
        accA.x = fmaf(v1, a1.x, accA.x); accA.y = fmaf(v1, a1.y, accA.y);
        accA.z = fmaf(v1, a1.z, accA.z); accA.w = fmaf(v1, a1.w, accA.w);
        accB.x = fmaf(v1, b1.x, accB.x); accB.y = fmaf(v1, b1.y, accB.y);
        accB.z = fmaf(v1, b1.z, accB.z); accB.w = fmaf(v1, b1.w, accB.w);
        accA.x = fmaf(v2, a2.x, accA.x); accA.y = fmaf(v2, a2.y, accA.y);
        accA.z = fmaf(v2, a2.z, accA.z); accA.w = fmaf(v2, a2.w, accA.w);
        accB.x = fmaf(v2, b2.x, accB.x); accB.y = fmaf(v2, b2.y, accB.y);
        accB.z = fmaf(v2, b2.z, accB.z); accB.w = fmaf(v2, b2.w, accB.w);
        accA.x = fmaf(v3, a3.x, accA.x); accA.y = fmaf(v3, a3.y, accA.y);
        accA.z = fmaf(v3, a3.z, accA.z); accA.w = fmaf(v3, a3.w, accA.w);
        accB.x = fmaf(v3, b3.x, accB.x); accB.y = fmaf(v3, b3.y, accB.y);
        accB.z = fmaf(v3, b3.z, accB.z); accB.w = fmaf(v3, b3.w, accB.w);

        c0 = n0; c1 = n1; c2 = n2; c3 = n3;
    }

    {   // final chunk (padding edges: val=0 -> no-op FMAs)
        const float4* r0 = Q4 + (size_t)c0.x * 16 + p0;
        const float4* r1 = Q4 + (size_t)c1.x * 16 + p0;
        const float4* r2 = Q4 + (size_t)c2.x * 16 + p0;
        const float4* r3 = Q4 + (size_t)c3.x * 16 + p0;
        const float4 a0 = __ldg(r0), b0 = __ldg(r0 + 1);
        const float4 a1 = __ldg(r1), b1 = __ldg(r1 + 1);
        const float4 a2 = __ldg(r2), b2 = __ldg(r2 + 1);
        const float4 a3 = __ldg(r3), b3 = __ldg(r3 + 1);
        const float v0 = __int_as_float(c0.y);
        const float v1 = __int_as_float(c1.y);
        const float v2 = __int_as_float(c2.y);
        const float v3 = __int_as_float(c3.y);

        accA.x = fmaf(v0, a0.x, accA.x); accA.y = fmaf(v0, a0.y, accA.y);
        accA.z = fmaf(v0, a0.z, accA.z); accA.w = fmaf(v0, a0.w, accA.w);
        accB.x = fmaf(v0, b0.x, accB.x); accB.y = fmaf(v0, b0.y, accB.y);
        accB.z = fmaf(v0, b0.z, accB.z); accB.w = fmaf(v0, b0.w, accB.w);
        accA.x = fmaf(v1, a1.x, accA.x); accA.y = fmaf(v1, a1.y, accA.y);
        accA.z = fmaf(v1, a1.z, accA.z); accA.w = fmaf(v1, a1.w, accA.w);
        accB.x = fmaf(v1, b1.x, accB.x); accB.y = fmaf(v1, b1.y, accB.y);
        accB.z = fmaf(v1, b1.z, accB.z); accB.w = fmaf(v1, b1.w, accB.w);
        accA.x = fmaf(v2, a2.x, accA.x); accA.y = fmaf(v2, a2.y, accA.y);
        accA.z = fmaf(v2, a2.z, accA.z); accA.w = fmaf(v2, a2.w, accA.w);
        accB.x = fmaf(v2, b2.x, accB.x); accB.y = fmaf(v2, b2.y, accB.y);
        accB.z = fmaf(v2, b2.z, accB.z); accB.w = fmaf(v2, b2.w, accB.w);
        accA.x = fmaf(v3, a3.x, accA.x); accA.y = fmaf(v3, a3.y, accA.y);
        accA.z = fmaf(v3, a3.z, accA.z); accA.w = fmaf(v3, a3.w, accA.w);
        accB.x = fmaf(v3, b3.x, accB.x); accB.y = fmaf(v3, b3.y, accB.y);
        accB.z = fmaf(v3, b3.z, accB.z); accB.w = fmaf(v3, b3.w, accB.w);
    }

    float4* orow = reinterpret_cast<float4*>(out) + (size_t)row * 16 + p0;
    float4 oA = orow[0], oB = orow[1];
    oA.x += accA.x; oA.y += accA.y; oA.z += accA.z; oA.w += accA.w;
    oB.x += accB.x; oB.y += accB.y; oB.z += accB.z; oB.w += accB.w;
    orow[0] = oA; orow[1] = oB;
}

extern "C" void kernel_launch(void* const* d_in, const int* in_sizes, int n_in,
                              void* d_out, int out_size)
{
    const int*   rows = (const int*)  d_in[0];
    const int*   cols = (const int*)  d_in[1];
    const float* vals = (const float*)d_in[2];
    const float* X    = (const float*)d_in[3];
    const float* W1   = (const float*)d_in[4];
    const float* b1   = (const float*)d_in[5];
    const float* W2   = (const float*)d_in[6];
    const float* b2   = (const float*)d_in[7];
    float* out = (float*)d_out;

    const int E = in_sizes[0];
    const int N = in_sizes[3] / FDIM;

    cudaFuncSetAttribute(gnn_dense_hist, cudaFuncAttributeMaxDynamicSharedMemorySize, 49152);

    void* p = nullptr;
    cudaGetSymbolAddress(&p, g_cnt);
    cudaMemsetAsync(p, 0, (size_t)N * sizeof(int));

    const int blocksD = (N + 63) / 64;
    gnn_dense_hist<<<blocksD, 256, 49152>>>(X, W1, b1, W2, b2, rows, out, N, E);

    const int nb = (N + 1023) / 1024;
    scan_blocksums<<<nb, 1024>>>(N);
    scan_write<<<nb, 1024>>>(N);

    gnn_scatter<<<(E + 255) / 256, 256>>>(rows, cols, vals, E);

    const long long work = (long long)N * 8;
    gnn_spmm_csr<<<(int)((work + 255) / 256), 256>>>(out, N);
}

// round 14
// speedup vs baseline: 1.0404x; 1.0404x over previous
#include <cuda_runtime.h>

#define MAX_N 100000
#define MAX_E 1200000
#define MAX_EP (MAX_E + 3 * MAX_N)   // padded bins: each row rounded up to 4
#define FDIM 64

__device__ float g_Q[(size_t)MAX_N * FDIM];      // Q = X@W1 + (X*X)@W2
__device__ int   g_cnt[MAX_N];                   // per-row edge count
__device__ int   g_rowstart[MAX_N];              // exclusive scan of padded counts
__device__ int   g_cursor[MAX_N];                // scatter cursor
__device__ int2  g_edges[MAX_EP];                // binned (col, val), zero-padded to x4
__device__ int   g_bsum[128];                    // block sums for the scan

// ---- packed f32x2 helpers (sm_103a FFMA2: 2 fp32 FMAs / issue slot) ----
typedef unsigned long long u64;
__device__ __forceinline__ u64 pack2(float lo, float hi) {
    u64 r; asm("mov.b64 %0, {%1, %2};" : "=l"(r) : "f"(lo), "f"(hi)); return r;
}
__device__ __forceinline__ void unpack2(u64 p, float& lo, float& hi) {
    asm("mov.b64 {%0, %1}, %2;" : "=f"(lo), "=f"(hi) : "l"(p));
}
__device__ __forceinline__ u64 fma2(u64 a, u64 b, u64 c) {
    u64 d; asm("fma.rn.f32x2 %0, %1, %2, %3;" : "=l"(d) : "l"(a), "l"(b), "l"(c)); return d;
}
__device__ __forceinline__ u64 mul2(u64 a, u64 b) {
    u64 d; asm("mul.rn.f32x2 %0, %1, %2;" : "=l"(d) : "l"(a), "l"(b)); return d;
}

// ---------------------------------------------------------------------------
// Dense GEMM (f32x2) + fused histogram. (R8/R12 measured-best, byte-identical)
// ---------------------------------------------------------------------------
__global__ __launch_bounds__(256, 3) void gnn_dense_hist(
    const float* __restrict__ X,
    const float* __restrict__ W1, const float* __restrict__ b1,
    const float* __restrict__ W2, const float* __restrict__ b2,
    const int* __restrict__ rows,
    float* __restrict__ out, int N, int E)
{
    extern __shared__ float smem[];
    float* W1s = smem;          // 64*64 = 16KB
    float* W2s = smem + 4096;   // 16KB
    float* Xs  = smem + 8192;   // 64*64 = 16KB

    const int tid = threadIdx.x;

    #pragma unroll
    for (int i = tid; i < 1024; i += 256) {
        reinterpret_cast<float4*>(W1s)[i] = reinterpret_cast<const float4*>(W1)[i];
        reinterpret_cast<float4*>(W2s)[i] = reinterpret_cast<const float4*>(W2)[i];
    }

    const int row0 = blockIdx.x * 64;
    #pragma unroll
    for (int i = tid; i < 64 * 16; i += 256) {
        const int r  = i >> 4;
        const int gr = row0 + r;
        float4 v = make_float4(0.f, 0.f, 0.f, 0.f);
        if (gr < N) v = reinterpret_cast<const float4*>(X)[(size_t)gr * 16 + (i & 15)];
        reinterpret_cast<float4*>(Xs)[i] = v;
    }

    const int stride = gridDim.x * 256;
    for (int e = blockIdx.x * 256 + tid; e < E; e += stride)
        atomicAdd(&g_cnt[__ldg(rows + e)], 1);

    __syncthreads();

    const int rg  = (tid >> 4) * 4;
    const int cg4 = tid & 15;

    const u64* W1p = reinterpret_cast<const u64*>(W1s);
    const u64* W2p = reinterpret_cast<const u64*>(W2s);

    u64 acc1a[4], acc1b[4], acc2a[4], acc2b[4];
    #pragma unroll
    for (int i = 0; i < 4; ++i) { acc1a[i]=0; acc1b[i]=0; acc2a[i]=0; acc2b[i]=0; }

    #pragma unroll 8
    for (int k = 0; k < 64; ++k) {
        const u64 w1a = W1p[k * 32 + 2 * cg4];
        const u64 w1b = W1p[k * 32 + 2 * cg4 + 1];
        const u64 w2a = W2p[k * 32 + 2 * cg4];
        const u64 w2b = W2p[k * 32 + 2 * cg4 + 1];
        #pragma unroll
        for (int i = 0; i < 4; ++i) {
            const float x  = Xs[(rg + i) * 64 + k];
            const u64 xp  = pack2(x, x);
            const u64 xsq = mul2(xp, xp);
            acc1a[i] = fma2(xp,  w1a, acc1a[i]);
            acc1b[i] = fma2(xp,  w1b, acc1b[i]);
            acc2a[i] = fma2(xsq, w2a, acc2a[i]);
            acc2b[i] = fma2(xsq, w2b, acc2b[i]);
        }
    }

    const int cc = cg4 * 4;
    float4 bb;
    bb.x = __ldg(b1 + cc + 0) + __ldg(b2 + cc + 0);
    bb.y = __ldg(b1 + cc + 1) + __ldg(b2 + cc + 1);
    bb.z = __ldg(b1 + cc + 2) + __ldg(b2 + cc + 2);
    bb.w = __ldg(b1 + cc + 3) + __ldg(b2 + cc + 3);

    #pragma unroll
    for (int i = 0; i < 4; ++i) {
        const int gr = row0 + rg + i;
        if (gr < N) {
            float a10, a11, a12, a13, a20, a21, a22, a23;
            unpack2(acc1a[i], a10, a11);
            unpack2(acc1b[i], a12, a13);
            unpack2(acc2a[i], a20, a21);
            unpack2(acc2b[i], a22, a23);
            float4 o, q;
            o.x = a10 + bb.x;  q.x = a10 + a20;
            o.y = a11 + bb.y;  q.y = a11 + a21;
            o.z = a12 + bb.z;  q.z = a12 + a22;
            o.w = a13 + bb.w;  q.w = a13 + a23;
            reinterpret_cast<float4*>(out)[(size_t)gr * 16 + cg4] = o;
            reinterpret_cast<float4*>(g_Q)[(size_t)gr * 16 + cg4] = q;
        }
    }
}

// ---------------------------------------------------------------------------
// Scan stage (R12 structure, byte-identical): padded counts vp = (cnt+3)&~3.
// ---------------------------------------------------------------------------
__device__ __forceinline__ int warp_incl_scan(int v) {
    #pragma unroll
    for (int off = 1; off < 32; off <<= 1) {
        int u = __shfl_up_sync(0xffffffffu, v, off);
        if ((threadIdx.x & 31) >= off) v += u;
    }
    return v;
}

__global__ __launch_bounds__(1024) void scan_blocksums(int N) {
    const int i = blockIdx.x * 1024 + threadIdx.x;
    int v = (i < N) ? ((g_cnt[i] + 3) & ~3) : 0;
    #pragma unroll
    for (int off = 16; off > 0; off >>= 1)
        v += __shfl_down_sync(0xffffffffu, v, off);
    __shared__ int ws[32];
    const int lane = threadIdx.x & 31, wid = threadIdx.x >> 5;
    if (lane == 0) ws[wid] = v;
    __syncthreads();
    if (wid == 0) {
        int x = ws[lane];
        #pragma unroll
        for (int off = 16; off > 0; off >>= 1)
            x += __shfl_down_sync(0xffffffffu, x, off);
        if (lane == 0) g_bsum[blockIdx.x] = x;
    }
}

__global__ __launch_bounds__(128) void scan_bsums(int nb) {
    __shared__ int s[128];
    const int t = threadIdx.x;
    s[t] = (t < nb) ? g_bsum[t] : 0;
    __syncthreads();
    #pragma unroll
    for (int off = 1; off < 128; off <<= 1) {
        int v = (t >= off) ? s[t - off] : 0;
        __syncthreads();
        s[t] += v;
        __syncthreads();
    }
    if (t < nb) g_bsum[t] = s[t];
}

__global__ __launch_bounds__(1024) void scan_write(int N) {
    const int t = threadIdx.x, b = blockIdx.x;
    const int i = b * 1024 + t;
    const int cnt = (i < N) ? g_cnt[i] : 0;
    const int vp  = (cnt + 3) & ~3;
    const int lane = t & 31, wid = t >> 5;
    int inc = warp_incl_scan(vp);
    __shared__ int ws[32];
    if (lane == 31) ws[wid] = inc;
    __syncthreads();
    if (wid == 0) {
        int x = ws[lane];
        x = warp_incl_scan(x);
        ws[lane] = x;
    }
    __syncthreads();
    int excl = inc - vp + (wid ? ws[wid - 1] : 0) + (b ? g_bsum[b - 1] : 0);
    if (i < N) {
        g_rowstart[i] = excl;
        g_cursor[i]   = excl;
        const int2 z = make_int2(0, 0);
        for (int p = excl + cnt; p < excl + vp; ++p) g_edges[p] = z;
    }
}

// ---------------------------------------------------------------------------
// Scatter: 4 edges per thread in strided layout -> 4 independent
// atomic->store chains (R13 profile: issue 5%, atomic-latency bound).
// ---------------------------------------------------------------------------
__global__ __launch_bounds__(256) void gnn_scatter(
    const int* __restrict__ rows,
    const int* __restrict__ cols,
    const float* __restrict__ vals, int E, int T)
{
    const int t = blockIdx.x * blockDim.x + threadIdx.x;
    if (t >= T) return;

    #pragma unroll
    for (int u = 0; u < 4; ++u) {
        const int e = t + u * T;
        if (e < E) {
            const int r   = __ldg(rows + e);
            const int pos = atomicAdd(&g_cursor[r], 1);
            g_edges[pos] = make_int2(__ldg(cols + e),
                                     __float_as_int(__ldg(vals + e)));
        }
    }
}

// ---------------------------------------------------------------------------
// CSR SpMM: 16 lanes/row, float4/lane, padded bins, edge prefetch.
// (R12 measured-best, byte-identical)
// ---------------------------------------------------------------------------
__global__ __launch_bounds__(256) void gnn_spmm_csr(float* __restrict__ out, int N)
{
    const int gid = blockIdx.x * blockDim.x + threadIdx.x;
    const int row = gid >> 4;
    if (row >= N) return;
    const int lane16 = gid & 15;

    const int start = __ldg(g_rowstart + row);
    const int end   = __ldg(g_cursor + row);      // = start + cnt
    const int deg   = end - start;
    if (deg <= 0) return;
    int iters = (deg + 3) >> 2;

    const float4* __restrict__ Q4 = reinterpret_cast<const float4*>(g_Q);
    const int2* ep = g_edges + start;

    int2 c0 = __ldg(ep + 0), c1 = __ldg(ep + 1);
    int2 c2 = __ldg(ep + 2), c3 = __ldg(ep + 3);

    float4 acc = make_float4(0.f, 0.f, 0.f, 0.f);

    while (--iters > 0) {
        ep += 4;
        const int2 n0 = __ldg(ep + 0), n1 = __ldg(ep + 1);
        const int2 n2 = __ldg(ep + 2), n3 = __ldg(ep + 3);

        const float4 q0 = __ldg(Q4 + (size_t)c0.x * 16 + lane16);
        const float4 q1 = __ldg(Q4 + (size_t)c1.x * 16 + lane16);
        const float4 q2 = __ldg(Q4 + (size_t)c2.x * 16 + lane16);
        const float4 q3 = __ldg(Q4 + (size_t)c3.x * 16 + lane16);
        const float v0 = __int_as_float(c0.y);
        const float v1 = __int_as_float(c1.y);
        const float v2 = __int_as_float(c2.y);
        const float v3 = __int_as_float(c3.y);
        acc.x = fmaf(v0, q0.x, acc.x); acc.y = fmaf(v0, q0.y, acc.y);
        acc.z = fmaf(v0, q0.z, acc.z); acc.w = fmaf(v0, q0.w, acc.w);
        acc.x = fmaf(v1, q1.x, acc.x); acc.y = fmaf(v1, q1.y, acc.y);
        acc.z = fmaf(v1, q1.z, acc.z); acc.w = fmaf(v1, q1.w, acc.w);
        acc.x = fmaf(v2, q2.x, acc.x); acc.y = fmaf(v2, q2.y, acc.y);
        acc.z = fmaf(v2, q2.z, acc.z); acc.w = fmaf(v2, q2.w, acc.w);
        acc.x = fmaf(v3, q3.x, acc.x); acc.y = fmaf(v3, q3.y, acc.y);
        acc.z = fmaf(v3, q3.z, acc.z); acc.w = fmaf(v3, q3.w, acc.w);

        c0 = n0; c1 = n1; c2 = n2; c3 = n3;
    }

    {   // final chunk (padding edges have val=0 -> no-op FMAs)
        const float4 q0 = __ldg(Q4 + (size_t)c0.x * 16 + lane16);
        const float4 q1 = __ldg(Q4 + (size_t)c1.x * 16 + lane16);
        const float4 q2 = __ldg(Q4 + (size_t)c2.x * 16 + lane16);
        const float4 q3 = __ldg(Q4 + (size_t)c3.x * 16 + lane16);
        const float v0 = __int_as_float(c0.y);
        const float v1 = __int_as_float(c1.y);
        const float v2 = __int_as_float(c2.y);
        const float v3 = __int_as_float(c3.y);
        acc.x = fmaf(v0, q0.x, acc.x); acc.y = fmaf(v0, q0.y, acc.y);
        acc.z = fmaf(v0, q0.z, acc.z); acc.w = fmaf(v0, q0.w, acc.w);
        acc.x = fmaf(v1, q1.x, acc.x); acc.y = fmaf(v1, q1.y, acc.y);
        acc.z = fmaf(v1, q1.z, acc.z); acc.w = fmaf(v1, q1.w, acc.w);
        acc.x = fmaf(v2, q2.x, acc.x); acc.y = fmaf(v2, q2.y, acc.y);
        acc.z = fmaf(v2, q2.z, acc.z); acc.w = fmaf(v2, q2.w, acc.w);
        acc.x = fmaf(v3, q3.x, acc.x); acc.y = fmaf(v3, q3.y, acc.y);
        acc.z = fmaf(v3, q3.z, acc.z); acc.w = fmaf(v3, q3.w, acc.w);
    }

    float4* orow = reinterpret_cast<float4*>(out) + (size_t)row * 16 + lane16;
    float4 o = *orow;
    o.x += acc.x; o.y += acc.y; o.z += acc.z; o.w += acc.w;
    *orow = o;
}

extern "C" void kernel_launch(void* const* d_in, const int* in_sizes, int n_in,
                              void* d_out, int out_size)
{
    const int*   rows = (const int*)  d_in[0];
    const int*   cols = (const int*)  d_in[1];
    const float* vals = (const float*)d_in[2];
    const float* X    = (const float*)d_in[3];
    const float* W1   = (const float*)d_in[4];
    const float* b1   = (const float*)d_in[5];
    const float* W2   = (const float*)d_in[6];
    const float* b2   = (const float*)d_in[7];
    float* out = (float*)d_out;

    const int E = in_sizes[0];
    const int N = in_sizes[3] / FDIM;

    cudaFuncSetAttribute(gnn_dense_hist, cudaFuncAttributeMaxDynamicSharedMemorySize, 49152);

    void* p = nullptr;
    cudaGetSymbolAddress(&p, g_cnt);
    cudaMemsetAsync(p, 0, (size_t)N * sizeof(int));

    const int blocksD = (N + 63) / 64;
    gnn_dense_hist<<<blocksD, 256, 49152>>>(X, W1, b1, W2, b2, rows, out, N, E);

    const int nb = (N + 1023) / 1024;
    scan_blocksums<<<nb, 1024>>>(N);
    scan_bsums<<<1, 128>>>(nb);
    scan_write<<<nb, 1024>>>(N);

    const int T = (E + 3) / 4;   // threads for scatter (4 edges each)
    gnn_scatter<<<(T + 255) / 256, 256>>>(rows, cols, vals, E, T);

    const long long work = (long long)N * 16;
    gnn_spmm_csr<<<(int)((work + 255) / 256), 256>>>(out, N);
}